// round 15
// baseline (speedup 1.0000x reference)
#include <cuda_runtime.h>
#include <cuda_fp16.h>
#include <math.h>
#include <stdint.h>

#define B_ROWS 32768
#define F_DIM  2668

// Big-GEMM K geometry. userid: fv cols [0,943). itemid: fv cols [943,2625),
// processed from aligned base col 940 with k in [3,1685) valid (mask edges).
#define KP1 960     // 30 chunks of 32
#define KP2 1696    // 53 chunks of 32
#define NC1 30
#define NC2 53

// ---------------------------------------------------------------------------
// Device scratch
// ---------------------------------------------------------------------------
__device__ float g_Ebig[(size_t)B_ROWS * 256];   // uu|ui|tu|ti
__device__ float g_Lin[2][B_ROWS];               // linear partials

// fp16 weights, [n][k] layout, k zero-padded.
__device__ __align__(16) __half g_Bh1[128 * KP1];
__device__ __align__(16) __half g_Bh2[128 * KP2];

// ---------------------------------------------------------------------------
// PTX helpers (base PTX, assemble at compute_103)
// ---------------------------------------------------------------------------
__device__ __forceinline__ uint32_t smem_u32(const void* p) {
    uint32_t a;
    asm("{ .reg .u64 t; cvta.to.shared.u64 t, %1; cvt.u32.u64 %0, t; }"
        : "=r"(a) : "l"(p));
    return a;
}

__device__ __forceinline__ void mma_f16(float* c, const uint32_t* a, const uint32_t* b) {
    asm volatile("mma.sync.aligned.m16n8k16.row.col.f32.f16.f16.f32 "
        "{%0,%1,%2,%3}, {%4,%5,%6,%7}, {%8,%9}, {%0,%1,%2,%3};"
        : "+f"(c[0]), "+f"(c[1]), "+f"(c[2]), "+f"(c[3])
        : "r"(a[0]), "r"(a[1]), "r"(a[2]), "r"(a[3]), "r"(b[0]), "r"(b[1]));
}

__device__ __forceinline__ void ldsm_x4(uint32_t* r, uint32_t addr) {
    asm volatile("ldmatrix.sync.aligned.m8n8.x4.shared.b16 {%0,%1,%2,%3}, [%4];"
        : "=r"(r[0]), "=r"(r[1]), "=r"(r[2]), "=r"(r[3]) : "r"(addr));
}

__device__ __forceinline__ void cp16(uint32_t dst, const void* src) {
    asm volatile("cp.async.cg.shared.global [%0], [%1], 16;" :: "r"(dst), "l"(src));
}
#define CP_COMMIT()  asm volatile("cp.async.commit_group;" ::: "memory")
#define CP_WAIT(n)   asm volatile("cp.async.wait_group %0;" :: "n"(n) : "memory")

// ---------------------------------------------------------------------------
// Prep: transpose big-embedding weights into fp16, [n][k] layout.
// itemid k index shifted by +3 (k stores W[k-3] for 3<=k<1685). Zero-padded.
// ---------------------------------------------------------------------------
__global__ __launch_bounds__(256)
void prep_B_kernel(const float* __restrict__ Wuu, const float* __restrict__ Wui,
                   const float* __restrict__ Wtu, const float* __restrict__ Wti)
{
    const int idx = blockIdx.x * 256 + threadIdx.x;
    const int N1 = 128 * KP1;
    if (idx < N1) {
        const int n = idx / KP1, k = idx % KP1;
        float v = 0.0f;
        if (k < 943) v = (n < 64) ? Wuu[k * 64 + n] : Wui[k * 64 + (n - 64)];
        g_Bh1[idx] = __float2half_rn(v);
    } else if (idx < N1 + 128 * KP2) {
        const int j = idx - N1;
        const int n = j / KP2, k = j % KP2;
        float v = 0.0f;
        if (k >= 3 && k < 1685)
            v = (n < 64) ? Wtu[(k - 3) * 64 + n] : Wti[(k - 3) * 64 + (n - 64)];
        g_Bh2[j] = __float2half_rn(v);
    }
}

// ---------------------------------------------------------------------------
// Plain-fp16 warp-MMA GEMM: A = fp16(fv), B = fp16(W), fp32 accumulation.
// 1 MMA per fragment pair. One syncthreads per chunk; A-conversion +
// B cp.async for chunk t+1 overlap the HMMA drain of chunk t.
// grid = 512: blocks [0,256) itemid (long, first), [256,512) userid.
// CTA: 512 threads = 16 warps, warp grid 4(M) x 4(N), warp tile 32x32.
// smem rows 80B: ldmatrix 8-row groups conflict-free.
// ---------------------------------------------------------------------------
#define SROW 80
#define ABYTES 10240               // 128 * 80
#define BUFSZ  (2 * ABYTES)        // AH, BH per buffer
#define AH_OFF(b) ((b) * BUFSZ)
#define BH_OFF(b) ((b) * BUFSZ + ABYTES)
#define LW_OFF    (2 * BUFSZ)                  // 40960
#define GEMM_SMEM (LW_OFF + KP2 * 4)           // 47744 bytes

// Convert one float4 to fp16 + linear-dot partial. Masked variant.
__device__ __forceinline__ float cvt_row_m(char* smem, uint32_t ah,
                                           int row, int col, float4 v, float4 lw,
                                           int gc0, int Klo, int Khi)
{
    float x0 = (gc0     >= Klo && gc0     < Khi) ? v.x : 0.0f;
    float x1 = (gc0 + 1 >= Klo && gc0 + 1 < Khi) ? v.y : 0.0f;
    float x2 = (gc0 + 2 >= Klo && gc0 + 2 < Khi) ? v.z : 0.0f;
    float x3 = (gc0 + 3 >= Klo && gc0 + 3 < Khi) ? v.w : 0.0f;
    float lin = fmaf(x0, lw.x, fmaf(x1, lw.y, fmaf(x2, lw.z, x3 * lw.w)));
    __half2 h0 = __floats2half2_rn(x0, x1);
    __half2 h1 = __floats2half2_rn(x2, x3);
    const uint32_t off = row * SROW + col * 2;
    *(__half2*)(smem + ah + off)     = h0;
    *(__half2*)(smem + ah + off + 4) = h1;
    return lin;
}

// Unmasked fast path (interior chunks).
__device__ __forceinline__ float cvt_row_f(char* smem, uint32_t ah,
                                           int row, int col, float4 v, float4 lw)
{
    float lin = fmaf(v.x, lw.x, fmaf(v.y, lw.y, fmaf(v.z, lw.z, v.w * lw.w)));
    __half2 h0 = __floats2half2_rn(v.x, v.y);
    __half2 h1 = __floats2half2_rn(v.z, v.w);
    const uint32_t off = row * SROW + col * 2;
    *(__half2*)(smem + ah + off)     = h0;
    *(__half2*)(smem + ah + off + 4) = h1;
    return lin;
}

__global__ __launch_bounds__(512)
void gemm_mma_kernel(const float* __restrict__ fv, const float* __restrict__ lnw)
{
    extern __shared__ __align__(16) char smem[];
    const uint32_t sb = smem_u32(smem);
    const int tid = threadIdx.x, lane = tid & 31, wid = tid >> 5;
    const int warp_m = (wid & 3) * 32, warp_n = (wid >> 2) * 32;

    const int g     = (blockIdx.x < 256) ? 1 : 0;   // itemid first (load balance)
    const int mtile = blockIdx.x & 255;
    const int Klo = g ? 3 : 0, Khi = g ? 1685 : 943;
    const int KP  = g ? KP2 : KP1, nc = g ? NC2 : NC1;
    const int colOff = g ? 128 : 0;
    const __half* __restrict__ Bh = g ? g_Bh2 : g_Bh1;
    const float* __restrict__ Abase = fv + (size_t)(mtile * 128) * F_DIM + (g ? 940 : 0);
    const float* __restrict__ lwb   = lnw + (g ? 940 : 0);

    // stage (masked) linw slice
    float* lw_s = (float*)(smem + LW_OFF);
    for (int k = tid; k < KP; k += 512)
        lw_s[k] = (k >= Klo && k < Khi) ? lwb[k] : 0.0f;

    // A: 2 float4/thread (rows arow0, arow0+64)
    const int arow0 = tid >> 3;
    const int acol  = (tid & 7) << 2;
    // B cp.async: 16B per thread
    const int bn  = tid >> 2;
    const int bk8 = (tid & 3) << 3;

    // ---- prologue: B(0) via cp.async, A(0) via registers, convert into buf0
    cp16(sb + BH_OFF(0) + bn * SROW + bk8 * 2, Bh + (size_t)bn * KP + bk8);
    CP_COMMIT();
    float4 r0 = *(const float4*)(Abase + (size_t)arow0 * F_DIM + acol);
    float4 r1 = *(const float4*)(Abase + (size_t)(arow0 + 64) * F_DIM + acol);

    __syncthreads();   // lw_s visible

    float lin0 = 0.0f, lin1 = 0.0f;
    {
        const float4 lw4 = *(const float4*)(lw_s + acol);
        lin0 += cvt_row_m(smem, AH_OFF(0), arow0,      acol, r0, lw4,
                          acol, Klo, Khi);
        lin1 += cvt_row_m(smem, AH_OFF(0), arow0 + 64, acol, r1, lw4,
                          acol, Klo, Khi);
    }
    // prefetch A(1)
    float4 av0 = *(const float4*)(Abase + (size_t)arow0 * F_DIM + 32 + acol);
    float4 av1 = *(const float4*)(Abase + (size_t)(arow0 + 64) * F_DIM + 32 + acol);

    CP_WAIT(0);
    __syncthreads();   // buf0 fully ready

    float acc[2][4][4];
    #pragma unroll
    for (int i = 0; i < 2; i++)
        #pragma unroll
        for (int j = 0; j < 4; j++)
            #pragma unroll
            for (int q = 0; q < 4; q++) acc[i][j][q] = 0.0f;

    const uint32_t aRowSel = (lane & 7) + ((lane >> 3) & 1) * 8;
    const uint32_t aKSel   = ((lane >> 4) & 1) * 8;

    for (int t = 0; t < nc; ++t) {
        const int b = t & 1;
        const bool hasN  = (t + 1 < nc);
        const bool hasN2 = (t + 2 < nc);

        // B(t+1) -> other buffer
        if (hasN) {
            const int k1 = (t + 1) << 5;
            cp16(sb + BH_OFF(b ^ 1) + bn * SROW + bk8 * 2, Bh + (size_t)bn * KP + k1 + bk8);
            CP_COMMIT();
        }
        // A(t+2) register prefetch
        float4 an0, an1;
        if (hasN2) {
            const int k2 = (t + 2) << 5;
            an0 = *(const float4*)(Abase + (size_t)arow0 * F_DIM + k2 + acol);
            an1 = *(const float4*)(Abase + (size_t)(arow0 + 64) * F_DIM + k2 + acol);
        }

        // ---- fragments + 16 HMMA for chunk t (tensor pipe drains async)
        #pragma unroll
        for (int ks = 0; ks < 32; ks += 16) {
            uint32_t ah[2][4], bh0[4], bh1[4];
            const uint32_t aoff = sb + AH_OFF(b)
                + (warp_m + aRowSel) * SROW + (ks + aKSel) * 2;
            ldsm_x4(ah[0], aoff);
            ldsm_x4(ah[1], aoff + 16 * SROW);
            const uint32_t boff = sb + BH_OFF(b) + (warp_n + lane) * SROW + ks * 2;
            ldsm_x4(bh0, boff);
            ldsm_x4(bh1, boff + 16);
            #pragma unroll
            for (int nf = 0; nf < 4; ++nf) {
                uint32_t bhf[2] = { bh0[nf], bh1[nf] };
                #pragma unroll
                for (int mf = 0; mf < 2; ++mf)
                    mma_f16(acc[mf][nf], ah[mf], bhf);
            }
        }

        // ---- convert A(t+1) into buf b^1 while HMMA drains
        if (hasN) {
            const int k1 = (t + 1) << 5;
            const float4 lw4 = *(const float4*)(lw_s + k1 + acol);
            if (k1 + 32 <= Khi && k1 >= Klo) {
                lin0 += cvt_row_f(smem, AH_OFF(b ^ 1), arow0,      acol, av0, lw4);
                lin1 += cvt_row_f(smem, AH_OFF(b ^ 1), arow0 + 64, acol, av1, lw4);
            } else {
                lin0 += cvt_row_m(smem, AH_OFF(b ^ 1), arow0,      acol, av0, lw4,
                                  k1 + acol, Klo, Khi);
                lin1 += cvt_row_m(smem, AH_OFF(b ^ 1), arow0 + 64, acol, av1, lw4,
                                  k1 + acol, Klo, Khi);
            }
            CP_WAIT(0);   // B(t+1) landed
        }
        __syncthreads();  // buf b^1 complete; buf b frag reads all done
        av0 = an0; av1 = an1;
    }

    // linear partial reduce (8 threads per row)
    #pragma unroll
    for (int o = 4; o > 0; o >>= 1) {
        lin0 += __shfl_down_sync(0xffffffffu, lin0, o, 8);
        lin1 += __shfl_down_sync(0xffffffffu, lin1, o, 8);
    }
    if ((tid & 7) == 0) {
        g_Lin[g][mtile * 128 + arow0]      = lin0;
        g_Lin[g][mtile * 128 + arow0 + 64] = lin1;
    }

    // write C
    #pragma unroll
    for (int mf = 0; mf < 2; ++mf) {
        const int row0 = mtile * 128 + warp_m + mf * 16 + (lane >> 2);
        #pragma unroll
        for (int nf = 0; nf < 4; ++nf) {
            const int col = colOff + warp_n + nf * 8 + ((lane & 3) << 1);
            float* p = g_Ebig + (size_t)row0 * 256 + col;
            *(float2*)p                     = make_float2(acc[mf][nf][0], acc[mf][nf][1]);
            *(float2*)(p + (size_t)8 * 256) = make_float2(acc[mf][nf][2], acc[mf][nf][3]);
        }
    }
}

// ---------------------------------------------------------------------------
// Epilogue: one warp per row. Reads fv cols [2625,2668) + g_Ebig + g_Lin only.
// ---------------------------------------------------------------------------
__global__ __launch_bounds__(256)
void epilogue_kernel(const float* __restrict__ fv,
                     const float* __restrict__ Wau, const float* __restrict__ Wai,
                     const float* __restrict__ Wgu, const float* __restrict__ Wgi,
                     const float* __restrict__ Wou, const float* __restrict__ Woi,
                     const float* __restrict__ Wmu, const float* __restrict__ Wmi,
                     const float* __restrict__ linw, const float* __restrict__ linb,
                     float* __restrict__ out)
{
    const int row  = (blockIdx.x * blockDim.x + threadIdx.x) >> 5;
    const int lane = threadIdx.x & 31;
    if (row >= B_ROWS) return;

    const float* r = fv + (size_t)row * F_DIM;

    // linear tail: cols [2625, 2668)
    float part = r[2625 + lane] * linw[2625 + lane];
    if (lane < 11) part += r[2657 + lane] * linw[2657 + lane];

    // small-feature values (broadcast, L1-hot)
    float fs[42];
    #pragma unroll
    for (int j = 0; j < 42; j++) fs[j] = r[2626 + j];

    const float* E = g_Ebig + (size_t)row * 256;

    float cross = 0.0f;
    #pragma unroll
    for (int h = 0; h < 2; h++) {
        const int d = lane + h * 32;

        float au = fs[0] * Wau[d];
        float ai = fs[0] * Wai[d];
        float gu = fs[0] * Wgu[d] + fs[1] * Wgu[64 + d];
        float gi = fs[0] * Wgi[d] + fs[1] * Wgi[64 + d];

        float ou = 0.0f, oi = 0.0f;
        #pragma unroll
        for (int j = 0; j < 21; j++) {
            ou = fmaf(fs[2 + j], Wou[j * 64 + d], ou);
            oi = fmaf(fs[2 + j], Woi[j * 64 + d], oi);
        }
        float mu = 0.0f, mi = 0.0f;
        #pragma unroll
        for (int j = 0; j < 19; j++) {
            mu = fmaf(fs[23 + j], Wmu[j * 64 + d], mu);
            mi = fmaf(fs[23 + j], Wmi[j * 64 + d], mi);
        }

        const float uu = E[d];
        const float ui = E[64 + d];
        const float tu = E[128 + d];
        const float ti = E[192 + d];

        const float ouu = ou + uu;
        const float mt  = mu + tu;
        cross += au * (gu + ouu)
               + gu * ouu
               + ou * uu
               + (ai + gi + oi + ui) * mt
               + mi * ti;
    }

    float tot = part + cross;
    #pragma unroll
    for (int o = 16; o > 0; o >>= 1)
        tot += __shfl_xor_sync(0xffffffffu, tot, o);

    if (lane == 0) {
        const float lin = g_Lin[0][row] + g_Lin[1][row];
        const float logit = tot + lin + linb[0];
        out[row] = 1.0f / (1.0f + expf(-logit));
    }
}

// ---------------------------------------------------------------------------
extern "C" void kernel_launch(void* const* d_in, const int* in_sizes, int n_in,
                              void* d_out, int out_size)
{
    const float* fv  = (const float*)d_in[0];
    const float* Wau = (const float*)d_in[1];
    const float* Wai = (const float*)d_in[2];
    const float* Wgu = (const float*)d_in[3];
    const float* Wgi = (const float*)d_in[4];
    const float* Wou = (const float*)d_in[5];
    const float* Woi = (const float*)d_in[6];
    const float* Wmu = (const float*)d_in[7];
    const float* Wmi = (const float*)d_in[8];
    const float* Wuu = (const float*)d_in[9];
    const float* Wui = (const float*)d_in[10];
    const float* Wtu = (const float*)d_in[11];
    const float* Wti = (const float*)d_in[12];
    const float* lnw = (const float*)d_in[13];
    const float* lnb = (const float*)d_in[14];
    float* out = (float*)d_out;

    static int smem_set = 0;
    if (!smem_set) {
        cudaFuncSetAttribute(gemm_mma_kernel,
                             cudaFuncAttributeMaxDynamicSharedMemorySize, GEMM_SMEM);
        smem_set = 1;
    }

    const int prepTotal = 128 * (KP1 + KP2);
    prep_B_kernel<<<(prepTotal + 255) / 256, 256>>>(Wuu, Wui, Wtu, Wti);

    gemm_mma_kernel<<<512, 512, GEMM_SMEM>>>(fv, lnw);

    epilogue_kernel<<<B_ROWS / 8, 256>>>(fv, Wau, Wai, Wgu, Wgi, Wou, Woi,
                                         Wmu, Wmi, lnw, lnb, out);
}

// round 17
// speedup vs baseline: 1.2061x; 1.2061x over previous
#include <cuda_runtime.h>
#include <cuda_fp16.h>
#include <math.h>
#include <stdint.h>

#define B_ROWS 32768
#define F_DIM  2668

// Big-GEMM K geometry. userid: fv cols [0,943). itemid: fv cols [943,2625),
// processed from aligned base col 940 with k in [3,1685) valid (mask edges).
#define KP1 960     // 15 chunks of 64
#define KP2 1728    // 27 chunks of 64
#define NC1 15
#define NC2 27

// ---------------------------------------------------------------------------
// Device scratch
// ---------------------------------------------------------------------------
__device__ float g_Ebig[(size_t)B_ROWS * 256];   // uu|ui|tu|ti
__device__ float g_Lin[2][B_ROWS];               // linear partials

// fp16 weights, [n][k] layout, k zero-padded.
__device__ __align__(16) __half g_Bh1[128 * KP1];
__device__ __align__(16) __half g_Bh2[128 * KP2];

// ---------------------------------------------------------------------------
// PTX helpers (base PTX, assemble at compute_103)
// ---------------------------------------------------------------------------
__device__ __forceinline__ uint32_t smem_u32(const void* p) {
    uint32_t a;
    asm("{ .reg .u64 t; cvta.to.shared.u64 t, %1; cvt.u32.u64 %0, t; }"
        : "=r"(a) : "l"(p));
    return a;
}

__device__ __forceinline__ void mma_f16(float* c, const uint32_t* a, const uint32_t* b) {
    asm volatile("mma.sync.aligned.m16n8k16.row.col.f32.f16.f16.f32 "
        "{%0,%1,%2,%3}, {%4,%5,%6,%7}, {%8,%9}, {%0,%1,%2,%3};"
        : "+f"(c[0]), "+f"(c[1]), "+f"(c[2]), "+f"(c[3])
        : "r"(a[0]), "r"(a[1]), "r"(a[2]), "r"(a[3]), "r"(b[0]), "r"(b[1]));
}

__device__ __forceinline__ void ldsm_x4(uint32_t* r, uint32_t addr) {
    asm volatile("ldmatrix.sync.aligned.m8n8.x4.shared.b16 {%0,%1,%2,%3}, [%4];"
        : "=r"(r[0]), "=r"(r[1]), "=r"(r[2]), "=r"(r[3]) : "r"(addr));
}

__device__ __forceinline__ void cp16(uint32_t dst, const void* src) {
    asm volatile("cp.async.cg.shared.global [%0], [%1], 16;" :: "r"(dst), "l"(src));
}
#define CP_COMMIT()  asm volatile("cp.async.commit_group;" ::: "memory")
#define CP_WAIT(n)   asm volatile("cp.async.wait_group %0;" :: "n"(n) : "memory")

// ---------------------------------------------------------------------------
// Prep: transpose big-embedding weights into fp16, [n][k] layout.
// itemid k index shifted by +3 (k stores W[k-3] for 3<=k<1685). Zero-padded.
// ---------------------------------------------------------------------------
__global__ __launch_bounds__(256)
void prep_B_kernel(const float* __restrict__ Wuu, const float* __restrict__ Wui,
                   const float* __restrict__ Wtu, const float* __restrict__ Wti)
{
    const int idx = blockIdx.x * 256 + threadIdx.x;
    const int N1 = 128 * KP1;
    if (idx < N1) {
        const int n = idx / KP1, k = idx % KP1;
        float v = 0.0f;
        if (k < 943) v = (n < 64) ? Wuu[k * 64 + n] : Wui[k * 64 + (n - 64)];
        g_Bh1[idx] = __float2half_rn(v);
    } else if (idx < N1 + 128 * KP2) {
        const int j = idx - N1;
        const int n = j / KP2, k = j % KP2;
        float v = 0.0f;
        if (k >= 3 && k < 1685)
            v = (n < 64) ? Wtu[(k - 3) * 64 + n] : Wti[(k - 3) * 64 + (n - 64)];
        g_Bh2[j] = __float2half_rn(v);
    }
}

// ---------------------------------------------------------------------------
// Plain-fp16 warp-MMA GEMM, K=64 chunks, forced 1 CTA/SM (smem padding).
// One syncthreads per 64-col chunk; A-conversion + B cp.async for chunk t+1
// overlap the HMMA drain of chunk t (32 MMAs/warp per chunk).
// grid = 512: blocks [0,256) itemid (long, first), [256,512) userid.
// CTA: 512 threads = 16 warps, warp grid 4(M) x 4(N), warp tile 32x32.
// SROW=144: ldmatrix 8-row phases hit distinct 16B banks (144 mod 128 = 16).
// ---------------------------------------------------------------------------
#define SROW 144
#define ATILE (128 * SROW)          // 18432
#define BUFSZ (2 * ATILE)           // AH + BH per buffer = 36864
#define AH_OFF(b) ((b) * BUFSZ)
#define BH_OFF(b) ((b) * BUFSZ + ATILE)
#define LW_OFF    (2 * BUFSZ)                  // 73728
// Pad dynamic smem past 114 KB so only ONE CTA fits per SM (kills the
// cross-CTA L1tex-queue contention that regressed R15).
#define GEMM_SMEM (132 * 1024)                 // 135168 (used: 80640)

// Convert one float4 to fp16 + linear-dot partial. Masked variant.
__device__ __forceinline__ float cvt_one_m(char* smem, uint32_t ah,
                                           int row, int col, float4 v, float4 lw,
                                           int gc0, int Klo, int Khi)
{
    float x0 = (gc0     >= Klo && gc0     < Khi) ? v.x : 0.0f;
    float x1 = (gc0 + 1 >= Klo && gc0 + 1 < Khi) ? v.y : 0.0f;
    float x2 = (gc0 + 2 >= Klo && gc0 + 2 < Khi) ? v.z : 0.0f;
    float x3 = (gc0 + 3 >= Klo && gc0 + 3 < Khi) ? v.w : 0.0f;
    float lin = fmaf(x0, lw.x, fmaf(x1, lw.y, fmaf(x2, lw.z, x3 * lw.w)));
    __half2 h0 = __floats2half2_rn(x0, x1);
    __half2 h1 = __floats2half2_rn(x2, x3);
    const uint32_t off = row * SROW + col * 2;
    *(__half2*)(smem + ah + off)     = h0;
    *(__half2*)(smem + ah + off + 4) = h1;
    return lin;
}

// Unmasked fast path (interior chunks).
__device__ __forceinline__ float cvt_one_f(char* smem, uint32_t ah,
                                           int row, int col, float4 v, float4 lw)
{
    float lin = fmaf(v.x, lw.x, fmaf(v.y, lw.y, fmaf(v.z, lw.z, v.w * lw.w)));
    __half2 h0 = __floats2half2_rn(v.x, v.y);
    __half2 h1 = __floats2half2_rn(v.z, v.w);
    const uint32_t off = row * SROW + col * 2;
    *(__half2*)(smem + ah + off)     = h0;
    *(__half2*)(smem + ah + off + 4) = h1;
    return lin;
}

__global__ __launch_bounds__(512)
void gemm_mma_kernel(const float* __restrict__ fv, const float* __restrict__ lnw)
{
    extern __shared__ __align__(16) char smem[];
    const uint32_t sb = smem_u32(smem);
    const int tid = threadIdx.x, lane = tid & 31, wid = tid >> 5;
    const int warp_m = (wid & 3) * 32, warp_n = (wid >> 2) * 32;

    const int g     = (blockIdx.x < 256) ? 1 : 0;   // itemid first (load balance)
    const int mtile = blockIdx.x & 255;
    const int Klo = g ? 3 : 0, Khi = g ? 1685 : 943;
    const int KP  = g ? KP2 : KP1, nc = g ? NC2 : NC1;
    const int colOff = g ? 128 : 0;
    const __half* __restrict__ Bh = g ? g_Bh2 : g_Bh1;
    const float* __restrict__ Abase = fv + (size_t)(mtile * 128) * F_DIM + (g ? 940 : 0);
    const float* __restrict__ lwb   = lnw + (g ? 940 : 0);

    // stage (masked) linw slice
    float* lw_s = (float*)(smem + LW_OFF);
    for (int k = tid; k < KP; k += 512)
        lw_s[k] = (k >= Klo && k < Khi) ? lwb[k] : 0.0f;

    // A: 4 float4/thread — row = tid>>2 (one row per 4 threads), cols cc0+16j
    const int arow = tid >> 2;
    const int cc0  = (tid & 3) << 2;
    // B cp.async: row bn = tid>>2, two 16B chunks per thread
    const int bn   = tid >> 2;
    const int bk8a = (tid & 3) << 3;        // 0,8,16,24
    const int bk8b = bk8a + 32;             // 32,40,48,56

    // ---- prologue: B(0) via cp.async, A(0) via registers, convert into buf0
    cp16(sb + BH_OFF(0) + bn * SROW + bk8a * 2, Bh + (size_t)bn * KP + bk8a);
    cp16(sb + BH_OFF(0) + bn * SROW + bk8b * 2, Bh + (size_t)bn * KP + bk8b);
    CP_COMMIT();
    float4 r[4];
    #pragma unroll
    for (int j = 0; j < 4; ++j)
        r[j] = *(const float4*)(Abase + (size_t)arow * F_DIM + cc0 + 16 * j);

    __syncthreads();   // lw_s visible

    float lin = 0.0f;
    #pragma unroll
    for (int j = 0; j < 4; ++j) {
        const int c = cc0 + 16 * j;
        const float4 lw4 = *(const float4*)(lw_s + c);
        lin += cvt_one_m(smem, AH_OFF(0), arow, c, r[j], lw4, c, Klo, Khi);
    }
    // prefetch A(1)
    float4 av[4];
    #pragma unroll
    for (int j = 0; j < 4; ++j)
        av[j] = *(const float4*)(Abase + (size_t)arow * F_DIM + 64 + cc0 + 16 * j);

    CP_WAIT(0);
    __syncthreads();   // buf0 fully ready

    float acc[2][4][4];
    #pragma unroll
    for (int i = 0; i < 2; i++)
        #pragma unroll
        for (int j = 0; j < 4; j++)
            #pragma unroll
            for (int q = 0; q < 4; q++) acc[i][j][q] = 0.0f;

    const uint32_t aRowSel = (lane & 7) + ((lane >> 3) & 1) * 8;
    const uint32_t aKSel   = ((lane >> 4) & 1) * 8;

    for (int t = 0; t < nc; ++t) {
        const int b = t & 1;
        const bool hasN  = (t + 1 < nc);
        const bool hasN2 = (t + 2 < nc);

        // B(t+1) -> other buffer
        if (hasN) {
            const int k1 = (t + 1) << 6;
            cp16(sb + BH_OFF(b ^ 1) + bn * SROW + bk8a * 2, Bh + (size_t)bn * KP + k1 + bk8a);
            cp16(sb + BH_OFF(b ^ 1) + bn * SROW + bk8b * 2, Bh + (size_t)bn * KP + k1 + bk8b);
            CP_COMMIT();
        }
        // A(t+2) register prefetch
        float4 an[4];
        if (hasN2) {
            const int k2 = (t + 2) << 6;
            #pragma unroll
            for (int j = 0; j < 4; ++j)
                an[j] = *(const float4*)(Abase + (size_t)arow * F_DIM + k2 + cc0 + 16 * j);
        }

        // ---- fragments + 32 HMMA for chunk t (tensor pipe drains async)
        #pragma unroll
        for (int ks = 0; ks < 64; ks += 16) {
            uint32_t ah[2][4], bh0[4], bh1[4];
            const uint32_t aoff = sb + AH_OFF(b)
                + (warp_m + aRowSel) * SROW + (ks + aKSel) * 2;
            ldsm_x4(ah[0], aoff);
            ldsm_x4(ah[1], aoff + 16 * SROW);
            const uint32_t boff = sb + BH_OFF(b) + (warp_n + lane) * SROW + ks * 2;
            ldsm_x4(bh0, boff);
            ldsm_x4(bh1, boff + 16);
            #pragma unroll
            for (int nf = 0; nf < 4; ++nf) {
                uint32_t bhf[2] = { bh0[nf], bh1[nf] };
                #pragma unroll
                for (int mf = 0; mf < 2; ++mf)
                    mma_f16(acc[mf][nf], ah[mf], bhf);
            }
        }

        // ---- convert A(t+1) into buf b^1 while HMMA drains
        if (hasN) {
            const int k1 = (t + 1) << 6;
            if (k1 >= Klo && k1 + 64 <= Khi) {
                #pragma unroll
                for (int j = 0; j < 4; ++j) {
                    const int c = cc0 + 16 * j;
                    const float4 lw4 = *(const float4*)(lw_s + k1 + c);
                    lin += cvt_one_f(smem, AH_OFF(b ^ 1), arow, c, av[j], lw4);
                }
            } else {
                #pragma unroll
                for (int j = 0; j < 4; ++j) {
                    const int c = cc0 + 16 * j;
                    const float4 lw4 = *(const float4*)(lw_s + k1 + c);
                    lin += cvt_one_m(smem, AH_OFF(b ^ 1), arow, c, av[j], lw4,
                                     k1 + c, Klo, Khi);
                }
            }
            CP_WAIT(0);   // B(t+1) landed
        }
        __syncthreads();  // buf b^1 complete; buf b frag reads all done
        #pragma unroll
        for (int j = 0; j < 4; ++j) av[j] = an[j];
    }

    // linear partial reduce (4 threads per row)
    lin += __shfl_down_sync(0xffffffffu, lin, 2, 4);
    lin += __shfl_down_sync(0xffffffffu, lin, 1, 4);
    if ((tid & 3) == 0)
        g_Lin[g][mtile * 128 + arow] = lin;

    // write C
    #pragma unroll
    for (int mf = 0; mf < 2; ++mf) {
        const int row0 = mtile * 128 + warp_m + mf * 16 + (lane >> 2);
        #pragma unroll
        for (int nf = 0; nf < 4; ++nf) {
            const int col = colOff + warp_n + nf * 8 + ((lane & 3) << 1);
            float* p = g_Ebig + (size_t)row0 * 256 + col;
            *(float2*)p                     = make_float2(acc[mf][nf][0], acc[mf][nf][1]);
            *(float2*)(p + (size_t)8 * 256) = make_float2(acc[mf][nf][2], acc[mf][nf][3]);
        }
    }
}

// ---------------------------------------------------------------------------
// Epilogue: one warp per row. Reads fv cols [2625,2668) + g_Ebig + g_Lin only.
// ---------------------------------------------------------------------------
__global__ __launch_bounds__(256)
void epilogue_kernel(const float* __restrict__ fv,
                     const float* __restrict__ Wau, const float* __restrict__ Wai,
                     const float* __restrict__ Wgu, const float* __restrict__ Wgi,
                     const float* __restrict__ Wou, const float* __restrict__ Woi,
                     const float* __restrict__ Wmu, const float* __restrict__ Wmi,
                     const float* __restrict__ linw, const float* __restrict__ linb,
                     float* __restrict__ out)
{
    const int row  = (blockIdx.x * blockDim.x + threadIdx.x) >> 5;
    const int lane = threadIdx.x & 31;
    if (row >= B_ROWS) return;

    const float* r = fv + (size_t)row * F_DIM;

    // linear tail: cols [2625, 2668)
    float part = r[2625 + lane] * linw[2625 + lane];
    if (lane < 11) part += r[2657 + lane] * linw[2657 + lane];

    // small-feature values (broadcast, L1-hot)
    float fs[42];
    #pragma unroll
    for (int j = 0; j < 42; j++) fs[j] = r[2626 + j];

    const float* E = g_Ebig + (size_t)row * 256;

    float cross = 0.0f;
    #pragma unroll
    for (int h = 0; h < 2; h++) {
        const int d = lane + h * 32;

        float au = fs[0] * Wau[d];
        float ai = fs[0] * Wai[d];
        float gu = fs[0] * Wgu[d] + fs[1] * Wgu[64 + d];
        float gi = fs[0] * Wgi[d] + fs[1] * Wgi[64 + d];

        float ou = 0.0f, oi = 0.0f;
        #pragma unroll
        for (int j = 0; j < 21; j++) {
            ou = fmaf(fs[2 + j], Wou[j * 64 + d], ou);
            oi = fmaf(fs[2 + j], Woi[j * 64 + d], oi);
        }
        float mu = 0.0f, mi = 0.0f;
        #pragma unroll
        for (int j = 0; j < 19; j++) {
            mu = fmaf(fs[23 + j], Wmu[j * 64 + d], mu);
            mi = fmaf(fs[23 + j], Wmi[j * 64 + d], mi);
        }

        const float uu = E[d];
        const float ui = E[64 + d];
        const float tu = E[128 + d];
        const float ti = E[192 + d];

        const float ouu = ou + uu;
        const float mt  = mu + tu;
        cross += au * (gu + ouu)
               + gu * ouu
               + ou * uu
               + (ai + gi + oi + ui) * mt
               + mi * ti;
    }

    float tot = part + cross;
    #pragma unroll
    for (int o = 16; o > 0; o >>= 1)
        tot += __shfl_xor_sync(0xffffffffu, tot, o);

    if (lane == 0) {
        const float lin = g_Lin[0][row] + g_Lin[1][row];
        const float logit = tot + lin + linb[0];
        out[row] = 1.0f / (1.0f + expf(-logit));
    }
}

// ---------------------------------------------------------------------------
extern "C" void kernel_launch(void* const* d_in, const int* in_sizes, int n_in,
                              void* d_out, int out_size)
{
    const float* fv  = (const float*)d_in[0];
    const float* Wau = (const float*)d_in[1];
    const float* Wai = (const float*)d_in[2];
    const float* Wgu = (const float*)d_in[3];
    const float* Wgi = (const float*)d_in[4];
    const float* Wou = (const float*)d_in[5];
    const float* Woi = (const float*)d_in[6];
    const float* Wmu = (const float*)d_in[7];
    const float* Wmi = (const float*)d_in[8];
    const float* Wuu = (const float*)d_in[9];
    const float* Wui = (const float*)d_in[10];
    const float* Wtu = (const float*)d_in[11];
    const float* Wti = (const float*)d_in[12];
    const float* lnw = (const float*)d_in[13];
    const float* lnb = (const float*)d_in[14];
    float* out = (float*)d_out;

    static int smem_set = 0;
    if (!smem_set) {
        cudaFuncSetAttribute(gemm_mma_kernel,
                             cudaFuncAttributeMaxDynamicSharedMemorySize, GEMM_SMEM);
        smem_set = 1;
    }

    const int prepTotal = 128 * (KP1 + KP2);
    prep_B_kernel<<<(prepTotal + 255) / 256, 256>>>(Wuu, Wui, Wtu, Wti);

    gemm_mma_kernel<<<512, 512, GEMM_SMEM>>>(fv, lnw);

    epilogue_kernel<<<B_ROWS / 8, 256>>>(fv, Wau, Wai, Wgu, Wgi, Wou, Woi,
                                         Wmu, Wmi, lnw, lnb, out);
}